// round 1
// baseline (speedup 1.0000x reference)
#include <cuda_runtime.h>
#include <cstdint>

// Problem constants (fixed by the reference).
#define BB 32
#define TT 2000
#define HH 512
#define LL 256
#define THRESH 0.95f

// Scratch (allocation-free rule: __device__ globals).
__device__ float g_walpha[BB * TT];     // rescaled alphas
__device__ int   g_seg_start[BB * LL];  // index of previous fire (-1 for token 0)
__device__ int   g_seg_end[BB * LL];    // fire frame of this token (-1 = invalid token)
__device__ float g_wcarry[BB * LL];     // remainds at previous fire
__device__ float g_wcur[BB * LL];       // dist_completion at this token's fire

// ---------------------------------------------------------------------------
// Kernel 1: per-batch alpha rescale + exact-f32 sequential CIF scan.
// One block per batch. Threads cooperate on the reduction/rescale; thread 0
// replays the reference recurrence bit-for-bit (same f32 op sequence).
// ---------------------------------------------------------------------------
__global__ void __launch_bounds__(256, 1) cif_scan_kernel(
    const float* __restrict__ alphas,   // [B,T]
    const int*   __restrict__ tlen)     // [B]
{
    __shared__ float  s_alpha[TT];
    __shared__ double s_red[256];

    const int b   = blockIdx.x;
    const int tid = threadIdx.x;

    // Load alphas to smem, accumulate in double (≈ correctly-rounded f32 sum).
    double local = 0.0;
    for (int t = tid; t < TT; t += 256) {
        float a = alphas[b * TT + t];
        s_alpha[t] = a;
        local += (double)a;
    }
    s_red[tid] = local;
    __syncthreads();
    for (int off = 128; off > 0; off >>= 1) {
        if (tid < off) s_red[tid] += s_red[tid + off];
        __syncthreads();
    }
    const float sum   = (float)s_red[0];
    const float scale = __fdiv_rn((float)tlen[b], sum);

    // Rescale in smem and spill to global for the gather kernel.
    for (int t = tid; t < TT; t += 256) {
        float w = __fmul_rn(s_alpha[t], scale);
        s_alpha[t] = w;
        g_walpha[b * TT + t] = w;
    }
    __syncthreads();

    if (tid == 0) {
        float integrate = 0.0f;
        float carry = 0.0f;
        int   prev  = -1;
        int   k     = 0;
        #pragma unroll 4
        for (int t = 0; t < TT; ++t) {
            const float a    = s_alpha[t];
            const float dist = __fsub_rn(1.0f, integrate);   // before add (ref order)
            const float ni   = __fadd_rn(integrate, a);
            const bool  fire = (ni >= THRESH);
            if (fire) {
                const float cur = dist;
                const float rem = __fsub_rn(a, cur);
                if (k < LL) {
                    const int id = b * LL + k;
                    g_seg_start[id] = prev;
                    g_seg_end[id]   = t;
                    g_wcarry[id]    = carry;
                    g_wcur[id]      = cur;
                }
                carry = rem;
                prev  = t;
                ++k;
            }
            integrate = fire ? __fsub_rn(ni, 1.0f) : ni;
        }
        for (; k < LL; ++k) g_seg_end[b * LL + k] = -1;
    }
}

// ---------------------------------------------------------------------------
// Kernel 2: materialize out[b,k,:] = wcarry*h[s] + sum alpha_t*h[t] + wcur*h[e]
// Grid (L, B); 128 threads; each thread owns 4 contiguous channels (float4).
// Streaming HBM-bound: hidden read ~once, output written once.
// ---------------------------------------------------------------------------
__global__ void __launch_bounds__(128) cif_gather_kernel(
    const float* __restrict__ hidden,   // [B,T,H]
    float* __restrict__ out)            // [B,L,H]
{
    const int k = blockIdx.x;
    const int b = blockIdx.y;
    const int id = b * LL + k;
    const int c  = threadIdx.x * 4;     // channel base

    float4 acc = make_float4(0.f, 0.f, 0.f, 0.f);

    const int e = g_seg_end[id];
    if (e >= 0) {
        const int   s  = g_seg_start[id];
        const float* hb = hidden + (size_t)b * TT * HH;
        const float* wa = g_walpha + b * TT;

        if (s >= 0) {
            const float w = g_wcarry[id];
            float4 h4 = *reinterpret_cast<const float4*>(hb + (size_t)s * HH + c);
            acc.x += w * h4.x; acc.y += w * h4.y; acc.z += w * h4.z; acc.w += w * h4.w;
        }
        #pragma unroll 2
        for (int t = s + 1; t < e; ++t) {
            const float w = wa[t];
            float4 h4 = *reinterpret_cast<const float4*>(hb + (size_t)t * HH + c);
            acc.x += w * h4.x; acc.y += w * h4.y; acc.z += w * h4.z; acc.w += w * h4.w;
        }
        {
            const float w = g_wcur[id];
            float4 h4 = *reinterpret_cast<const float4*>(hb + (size_t)e * HH + c);
            acc.x += w * h4.x; acc.y += w * h4.y; acc.z += w * h4.z; acc.w += w * h4.w;
        }
    }
    *reinterpret_cast<float4*>(out + ((size_t)b * LL + k) * HH + c) = acc;
}

// ---------------------------------------------------------------------------
extern "C" void kernel_launch(void* const* d_in, const int* in_sizes, int n_in,
                              void* d_out, int out_size)
{
    const float* hidden = (const float*)d_in[0];   // [B,T,H] f32
    const float* alphas = (const float*)d_in[1];   // [B,T]   f32
    const int*   tlen   = (const int*)  d_in[2];   // [B]     i32
    float* out = (float*)d_out;                    // [B,L,H] f32

    cif_scan_kernel<<<BB, 256>>>(alphas, tlen);
    dim3 grid(LL, BB);
    cif_gather_kernel<<<grid, 128>>>(hidden, out);
}

// round 2
// speedup vs baseline: 1.2794x; 1.2794x over previous
#include <cuda_runtime.h>
#include <cstdint>

// Problem constants (fixed by the reference).
#define BB 32
#define TT 2000
#define HH 512
#define LL 256
#define THRESH 0.95f

// Scratch (allocation-free rule: __device__ globals).
__device__ float g_walpha[BB * TT];   // rescaled alphas
__device__ int4  g_rec[BB * LL];      // {seg_start, seg_end, carry_bits, cur_bits}
__device__ int   g_cnt[BB];           // fires per batch (clamped to LL)

// ---------------------------------------------------------------------------
// Kernel 1: per-batch alpha rescale + branchless exact-f32 sequential scan.
// One block per batch. Threads cooperate on reduction/rescale; thread 0
// replays the reference recurrence with a 12-cycle FADD/FSETP/FSEL chain.
// All fire bookkeeping is off the critical chain (SELs + unconditional STS).
// ---------------------------------------------------------------------------
__global__ void __launch_bounds__(256, 1) cif_scan_kernel(
    const float* __restrict__ alphas,   // [B,T]
    const int*   __restrict__ tlen)     // [B]
{
    __shared__ __align__(16) float s_alpha[TT];
    __shared__ double s_red[256];
    __shared__ __align__(16) int4 s_rec[LL + 1];   // +1 = spill slot for k >= LL
    __shared__ int s_cnt;

    const int b   = blockIdx.x;
    const int tid = threadIdx.x;

    // Load alphas to smem, accumulate in double (≈ correctly-rounded f32 sum).
    double local = 0.0;
    for (int t = tid; t < TT; t += 256) {
        float a = alphas[b * TT + t];
        s_alpha[t] = a;
        local += (double)a;
    }
    s_red[tid] = local;
    __syncthreads();
    for (int off = 128; off > 0; off >>= 1) {
        if (tid < off) s_red[tid] += s_red[tid + off];
        __syncthreads();
    }
    const float sum   = (float)s_red[0];
    const float scale = __fdiv_rn((float)tlen[b], sum);

    // Rescale in smem and spill to global for the gather kernel.
    for (int t = tid; t < TT; t += 256) {
        float w = __fmul_rn(s_alpha[t], scale);
        s_alpha[t] = w;
        g_walpha[b * TT + t] = w;
    }
    __syncthreads();

    if (tid == 0) {
        float integ = 0.0f;
        float carry = 0.0f;
        int   prev  = -1;
        int   k     = 0;

        const float4* a4 = reinterpret_cast<const float4*>(s_alpha);
        float4 av = a4[0];

        for (int t4 = 0; t4 < TT / 4; ++t4) {
            float4 nxt = (t4 + 1 < TT / 4) ? a4[t4 + 1] : av;   // prefetch
            #pragma unroll
            for (int j = 0; j < 4; ++j) {
                const float a = (j == 0) ? av.x : (j == 1) ? av.y
                              : (j == 2) ? av.z : av.w;
                const float iold = integ;
                // --- critical chain: FADD -> FSETP(pred-as-data) -> FSEL ---
                const float ni  = __fadd_rn(integ, a);
                const bool  p   = (ni >= THRESH);
                const float nim = __fsub_rn(ni, 1.0f);
                // --- off-chain side values (exact reference op order) ---
                const float cur = __fsub_rn(1.0f, iold);   // dist_completion
                const float rem = __fsub_rn(a, cur);       // remainds

                // Unconditional record write; non-fire garbage is overwritten
                // by the next real fire, trailing garbage masked by s_cnt.
                const int slot = (k < LL) ? k : LL;
                int4 r;
                r.x = prev;
                r.y = t4 * 4 + j;
                r.z = __float_as_int(carry);
                r.w = __float_as_int(cur);
                s_rec[slot] = r;

                // Branchless state updates (parallel SEL chains).
                carry = p ? rem : carry;
                prev  = p ? (t4 * 4 + j) : prev;
                k     = p ? (k + 1) : k;
                integ = p ? nim : ni;
            }
            av = nxt;
        }
        s_cnt = (k < LL) ? k : LL;
    }
    __syncthreads();

    // Bulk copy records + count to global (gather guards with cnt).
    if (tid < LL) g_rec[b * LL + tid] = s_rec[tid];
    if (tid == 0) g_cnt[b] = s_cnt;
}

// ---------------------------------------------------------------------------
// Kernel 2: materialize out[b,k,:] = carry*h[s] + sum alpha_t*h[t] + cur*h[e]
// Grid (L, B); 128 threads; each thread owns 4 contiguous channels (float4).
// Streaming HBM-bound.
// ---------------------------------------------------------------------------
__global__ void __launch_bounds__(128) cif_gather_kernel(
    const float* __restrict__ hidden,   // [B,T,H]
    float* __restrict__ out)            // [B,L,H]
{
    const int k = blockIdx.x;
    const int b = blockIdx.y;
    const int c = threadIdx.x * 4;      // channel base

    float4 acc = make_float4(0.f, 0.f, 0.f, 0.f);

    if (k < g_cnt[b]) {
        const int4 r = g_rec[b * LL + k];
        const int   s  = r.x;
        const int   e  = r.y;
        const float wc = __int_as_float(r.z);
        const float we = __int_as_float(r.w);

        const float* hb = hidden + (size_t)b * TT * HH;
        const float* wa = g_walpha + b * TT;

        if (s >= 0) {
            const float4 h4 = *reinterpret_cast<const float4*>(hb + (size_t)s * HH + c);
            acc.x += wc * h4.x; acc.y += wc * h4.y; acc.z += wc * h4.z; acc.w += wc * h4.w;
        }
        #pragma unroll 4
        for (int t = s + 1; t < e; ++t) {
            const float w = wa[t];
            const float4 h4 = *reinterpret_cast<const float4*>(hb + (size_t)t * HH + c);
            acc.x += w * h4.x; acc.y += w * h4.y; acc.z += w * h4.z; acc.w += w * h4.w;
        }
        {
            const float4 h4 = *reinterpret_cast<const float4*>(hb + (size_t)e * HH + c);
            acc.x += we * h4.x; acc.y += we * h4.y; acc.z += we * h4.z; acc.w += we * h4.w;
        }
    }
    *reinterpret_cast<float4*>(out + ((size_t)b * LL + k) * HH + c) = acc;
}

// ---------------------------------------------------------------------------
extern "C" void kernel_launch(void* const* d_in, const int* in_sizes, int n_in,
                              void* d_out, int out_size)
{
    const float* hidden = (const float*)d_in[0];   // [B,T,H] f32
    const float* alphas = (const float*)d_in[1];   // [B,T]   f32
    const int*   tlen   = (const int*)  d_in[2];   // [B]     i32
    float* out = (float*)d_out;                    // [B,L,H] f32

    cif_scan_kernel<<<BB, 256>>>(alphas, tlen);
    dim3 grid(LL, BB);
    cif_gather_kernel<<<grid, 128>>>(hidden, out);
}

// round 3
// speedup vs baseline: 1.5702x; 1.2273x over previous
#include <cuda_runtime.h>
#include <cstdint>

// Problem constants (fixed by the reference).
#define BB 32
#define TT 2000
#define HH 512
#define LL 256
#define THRESH 0.95f
#define NTHR 256
#define FRAMES_PER_THR 8   // 256*8 = 2048 >= 2000

// Scratch (allocation-free rule: __device__ globals).
__device__ float g_walpha[BB * TT];   // rescaled alphas
__device__ int4  g_rec[BB * LL];      // {seg_start, seg_end, carry_bits, cur_bits}
__device__ int   g_cnt[BB];           // fires per batch (clamped to LL)

// ---------------------------------------------------------------------------
// Kernel 1: per-batch rescale + minimal serial recurrence + parallel rebuild.
//
// Serial thread stores only ni_t = fl(integ_{t-1} + a_t) per step (5 instrs:
// FADD, FSETP, FSUB, FSEL, STS.32). A 256-thread post-pass reconstructs fire
// flags, token indices (prefix sum), and the exact-f32 weights from ni_t.
// ---------------------------------------------------------------------------
__global__ void __launch_bounds__(NTHR, 1) cif_scan_kernel(
    const float* __restrict__ alphas,   // [B,T]
    const int*   __restrict__ tlen)     // [B]
{
    __shared__ __align__(16) float s_alpha[TT];
    __shared__ __align__(16) float s_ni[TT];
    __shared__ double s_red[NTHR];
    __shared__ int    s_tsum[NTHR];     // per-thread fire counts for scan
    __shared__ int    s_fidx[LL];       // frame index of fire k (k < LL)
    __shared__ int    s_cnt;

    const int b   = blockIdx.x;
    const int tid = threadIdx.x;

    // ---- Phase 1: load alphas, double-accumulate sum, rescale ----
    double local = 0.0;
    for (int t = tid; t < TT; t += NTHR) {
        float a = alphas[b * TT + t];
        s_alpha[t] = a;
        local += (double)a;
    }
    s_red[tid] = local;
    __syncthreads();
    for (int off = NTHR / 2; off > 0; off >>= 1) {
        if (tid < off) s_red[tid] += s_red[tid + off];
        __syncthreads();
    }
    const float sum   = (float)s_red[0];
    const float scale = __fdiv_rn((float)tlen[b], sum);

    for (int t = tid; t < TT; t += NTHR) {
        float w = __fmul_rn(s_alpha[t], scale);
        s_alpha[t] = w;
        g_walpha[b * TT + t] = w;
    }
    __syncthreads();

    // ---- Phase 2: minimal serial recurrence (thread 0) ----
    if (tid == 0) {
        float integ = 0.0f;
        const float4* a4 = reinterpret_cast<const float4*>(s_alpha);
        float4* n4 = reinterpret_cast<float4*>(s_ni);
        #pragma unroll 2
        for (int t4 = 0; t4 < TT / 4; ++t4) {
            const float4 av = a4[t4];
            float4 nv;
            {   // step 0
                const float ni  = __fadd_rn(integ, av.x);
                const float nim = __fsub_rn(ni, 1.0f);
                nv.x = ni;
                integ = (ni >= THRESH) ? nim : ni;
            }
            {   // step 1
                const float ni  = __fadd_rn(integ, av.y);
                const float nim = __fsub_rn(ni, 1.0f);
                nv.y = ni;
                integ = (ni >= THRESH) ? nim : ni;
            }
            {   // step 2
                const float ni  = __fadd_rn(integ, av.z);
                const float nim = __fsub_rn(ni, 1.0f);
                nv.z = ni;
                integ = (ni >= THRESH) ? nim : ni;
            }
            {   // step 3
                const float ni  = __fadd_rn(integ, av.w);
                const float nim = __fsub_rn(ni, 1.0f);
                nv.w = ni;
                integ = (ni >= THRESH) ? nim : ni;
            }
            n4[t4] = nv;   // one STS.128 per 4 steps, off-chain
        }
    }
    __syncthreads();

    // ---- Phase 3: parallel rebuild of fire records from ni_t ----
    // Blocked distribution: thread i owns frames [i*8, i*8+8).
    const int t0 = tid * FRAMES_PER_THR;
    int cnt_local = 0;
    #pragma unroll
    for (int j = 0; j < FRAMES_PER_THR; ++j) {
        const int t = t0 + j;
        if (t < TT && s_ni[t] >= THRESH) ++cnt_local;
    }
    s_tsum[tid] = cnt_local;
    __syncthreads();

    // Exclusive prefix sum over 256 thread counts (warp scan + warp of warps).
    {
        const int lane = tid & 31;
        const int wid  = tid >> 5;
        int v = s_tsum[tid];
        int x = v;
        #pragma unroll
        for (int d = 1; d < 32; d <<= 1) {
            int y = __shfl_up_sync(0xffffffffu, x, d);
            if (lane >= d) x += y;
        }
        // x = inclusive scan within warp
        __syncthreads();
        if (lane == 31) s_tsum[wid] = x;           // warp totals -> slots 0..7
        __syncthreads();
        int warp_base = 0;
        if (wid > 0) {
            #pragma unroll
            for (int w = 0; w < 8; ++w) warp_base += (w < wid) ? s_tsum[w] : 0;
        }
        int total = 0;
        #pragma unroll
        for (int w = 0; w < 8; ++w) total += s_tsum[w];
        __syncthreads();
        s_tsum[tid] = warp_base + x - v;           // exclusive prefix for thread
        if (tid == 0) s_cnt = (total < LL) ? total : LL;
    }
    __syncthreads();

    // Scatter fire frame indices into compacted array.
    {
        int k = s_tsum[tid];
        #pragma unroll
        for (int j = 0; j < FRAMES_PER_THR; ++j) {
            const int t = t0 + j;
            if (t < TT && s_ni[t] >= THRESH) {
                if (k < LL) s_fidx[k] = t;
                ++k;
            }
        }
    }
    __syncthreads();

    // Build records: rec[k] = {prev_fire, this_fire, carry_bits, cur_bits}
    // integ_{t-1} = (ni_{t-1} >= TH) ? fl(ni_{t-1} - 1) : ni_{t-1};  integ_{-1}=0
    const int cnt = s_cnt;
    if (tid < LL) {
        int4 r = make_int4(0, -1, 0, 0);
        if (tid < cnt) {
            const int t = s_fidx[tid];
            float iold = 0.0f;
            if (t > 0) {
                const float np = s_ni[t - 1];
                iold = (np >= THRESH) ? __fsub_rn(np, 1.0f) : np;
            }
            const float cur = __fsub_rn(1.0f, iold);
            float carry = 0.0f;
            int prev = -1;
            if (tid > 0) {
                prev = s_fidx[tid - 1];
                float piold = 0.0f;
                if (prev > 0) {
                    const float np = s_ni[prev - 1];
                    piold = (np >= THRESH) ? __fsub_rn(np, 1.0f) : np;
                }
                const float pcur = __fsub_rn(1.0f, piold);
                carry = __fsub_rn(s_alpha[prev], pcur);    // remainds at prev
            }
            r.x = prev;
            r.y = t;
            r.z = __float_as_int(carry);
            r.w = __float_as_int(cur);
        }
        g_rec[b * LL + tid] = r;
    }
    if (tid == 0) g_cnt[b] = cnt;
}

// ---------------------------------------------------------------------------
// Kernel 2: materialize out[b,k,:] = carry*h[s] + sum alpha_t*h[t] + cur*h[e]
// Grid (L, B); 128 threads; float4 per thread. Streaming HBM-bound.
// ---------------------------------------------------------------------------
__global__ void __launch_bounds__(128) cif_gather_kernel(
    const float* __restrict__ hidden,   // [B,T,H]
    float* __restrict__ out)            // [B,L,H]
{
    const int k = blockIdx.x;
    const int b = blockIdx.y;
    const int c = threadIdx.x * 4;      // channel base

    float4 acc = make_float4(0.f, 0.f, 0.f, 0.f);

    if (k < g_cnt[b]) {
        const int4 r = g_rec[b * LL + k];
        const int   s  = r.x;
        const int   e  = r.y;
        const float wc = __int_as_float(r.z);
        const float we = __int_as_float(r.w);

        const float* hb = hidden + (size_t)b * TT * HH;
        const float* wa = g_walpha + b * TT;

        if (s >= 0) {
            const float4 h4 = __ldcs(reinterpret_cast<const float4*>(hb + (size_t)s * HH + c));
            acc.x += wc * h4.x; acc.y += wc * h4.y; acc.z += wc * h4.z; acc.w += wc * h4.w;
        }
        #pragma unroll 4
        for (int t = s + 1; t < e; ++t) {
            const float w = wa[t];
            const float4 h4 = __ldcs(reinterpret_cast<const float4*>(hb + (size_t)t * HH + c));
            acc.x += w * h4.x; acc.y += w * h4.y; acc.z += w * h4.z; acc.w += w * h4.w;
        }
        {
            const float4 h4 = __ldcs(reinterpret_cast<const float4*>(hb + (size_t)e * HH + c));
            acc.x += we * h4.x; acc.y += we * h4.y; acc.z += we * h4.z; acc.w += we * h4.w;
        }
    }
    __stcs(reinterpret_cast<float4*>(out + ((size_t)b * LL + k) * HH + c), acc);
}

// ---------------------------------------------------------------------------
extern "C" void kernel_launch(void* const* d_in, const int* in_sizes, int n_in,
                              void* d_out, int out_size)
{
    const float* hidden = (const float*)d_in[0];   // [B,T,H] f32
    const float* alphas = (const float*)d_in[1];   // [B,T]   f32
    const int*   tlen   = (const int*)  d_in[2];   // [B]     i32
    float* out = (float*)d_out;                    // [B,L,H] f32

    cif_scan_kernel<<<BB, NTHR>>>(alphas, tlen);
    dim3 grid(LL, BB);
    cif_gather_kernel<<<grid, 128>>>(hidden, out);
}

// round 6
// speedup vs baseline: 1.6214x; 1.0326x over previous
#include <cuda_runtime.h>
#include <cstdint>

// Problem constants (fixed by the reference).
#define BB 32
#define TT 2000
#define LL 256
#define HH 512
#define THRESH 0.95f
#define NTHR 256
#define FRAMES_PER_THR 8   // 256*8 = 2048 >= 2000
#define T4 (TT / 4)        // 500 float4 groups

// Scratch (allocation-free rule: __device__ globals).
__device__ float g_walpha[BB * TT];   // rescaled alphas
__device__ int4  g_rec[BB * LL];      // {seg_start, seg_end, carry_bits, cur_bits}
__device__ int   g_cnt[BB];           // fires per batch (clamped to LL)

// ---------------------------------------------------------------------------
// Kernel 1: per-batch rescale + minimal serial recurrence + parallel rebuild.
// ---------------------------------------------------------------------------
__global__ void __launch_bounds__(NTHR, 1) cif_scan_kernel(
    const float* __restrict__ alphas,   // [B,T]
    const int*   __restrict__ tlen)     // [B]
{
    __shared__ __align__(16) float s_alpha[TT];
    __shared__ __align__(16) float s_ni[TT];
    __shared__ double s_wred[8];
    __shared__ float  s_scale;
    __shared__ int    s_tsum[NTHR];
    __shared__ int    s_fidx[LL];
    __shared__ int    s_cnt;

    const int b    = blockIdx.x;
    const int tid  = threadIdx.x;
    const int lane = tid & 31;
    const int wid  = tid >> 5;

    // ---- Phase 1: load alphas (float4), double sum via warp shuffles ----
    const float4* ain = reinterpret_cast<const float4*>(alphas + b * TT);
    float4* asm4 = reinterpret_cast<float4*>(s_alpha);
    double local = 0.0;
    #pragma unroll
    for (int i = 0; i < 2; ++i) {
        const int idx = tid + i * NTHR;
        if (idx < T4) {
            const float4 v = ain[idx];
            asm4[idx] = v;
            local += (double)v.x + (double)v.y + (double)v.z + (double)v.w;
        }
    }
    #pragma unroll
    for (int off = 16; off > 0; off >>= 1)
        local += __shfl_down_sync(0xffffffffu, local, off);
    if (lane == 0) s_wred[wid] = local;
    __syncthreads();
    if (tid == 0) {
        double s = 0.0;
        #pragma unroll
        for (int w = 0; w < 8; ++w) s += s_wred[w];
        s_scale = __fdiv_rn((float)tlen[b], (float)s);
    }
    __syncthreads();

    // ---- Rescale (smem + spill to global) ----
    const float scale = s_scale;
    float4* wout = reinterpret_cast<float4*>(g_walpha + b * TT);
    #pragma unroll
    for (int i = 0; i < 2; ++i) {
        const int idx = tid + i * NTHR;
        if (idx < T4) {
            float4 v = asm4[idx];
            v.x = __fmul_rn(v.x, scale); v.y = __fmul_rn(v.y, scale);
            v.z = __fmul_rn(v.z, scale); v.w = __fmul_rn(v.w, scale);
            asm4[idx] = v;
            wout[idx] = v;
        }
    }
    __syncthreads();

    // ---- Phase 2: minimal serial recurrence (thread 0), prefetched ----
    if (tid == 0) {
        float integ = 0.0f;
        const float4* a4 = reinterpret_cast<const float4*>(s_alpha);
        float4* n4 = reinterpret_cast<float4*>(s_ni);
        float4 av = a4[0];
        #pragma unroll 2
        for (int t4 = 0; t4 < T4; ++t4) {
            const int nidx = (t4 + 1 < T4) ? t4 + 1 : t4;
            const float4 nx = a4[nidx];       // prefetch off-chain
            float4 nv;
            {   const float ni  = __fadd_rn(integ, av.x);
                const float nim = __fsub_rn(ni, 1.0f);
                nv.x = ni;
                integ = (ni >= THRESH) ? nim : ni; }
            {   const float ni  = __fadd_rn(integ, av.y);
                const float nim = __fsub_rn(ni, 1.0f);
                nv.y = ni;
                integ = (ni >= THRESH) ? nim : ni; }
            {   const float ni  = __fadd_rn(integ, av.z);
                const float nim = __fsub_rn(ni, 1.0f);
                nv.z = ni;
                integ = (ni >= THRESH) ? nim : ni; }
            {   const float ni  = __fadd_rn(integ, av.w);
                const float nim = __fsub_rn(ni, 1.0f);
                nv.w = ni;
                integ = (ni >= THRESH) ? nim : ni; }
            n4[t4] = nv;
            av = nx;
        }
    }
    __syncthreads();

    // ---- Phase 3: parallel rebuild of fire records from ni_t ----
    const int t0 = tid * FRAMES_PER_THR;
    int cnt_local = 0;
    #pragma unroll
    for (int j = 0; j < FRAMES_PER_THR; ++j) {
        const int t = t0 + j;
        if (t < TT && s_ni[t] >= THRESH) ++cnt_local;
    }
    s_tsum[tid] = cnt_local;
    __syncthreads();

    {   // exclusive prefix sum over 256 counts
        int v = s_tsum[tid];
        int x = v;
        #pragma unroll
        for (int d = 1; d < 32; d <<= 1) {
            int y = __shfl_up_sync(0xffffffffu, x, d);
            if (lane >= d) x += y;
        }
        __syncthreads();
        if (lane == 31) s_tsum[wid] = x;
        __syncthreads();
        int warp_base = 0, total = 0;
        #pragma unroll
        for (int w = 0; w < 8; ++w) {
            const int wv = s_tsum[w];
            warp_base += (w < wid) ? wv : 0;
            total += wv;
        }
        __syncthreads();
        s_tsum[tid] = warp_base + x - v;
        if (tid == 0) s_cnt = (total < LL) ? total : LL;
    }
    __syncthreads();

    {   // compact fire frame indices
        int k = s_tsum[tid];
        #pragma unroll
        for (int j = 0; j < FRAMES_PER_THR; ++j) {
            const int t = t0 + j;
            if (t < TT && s_ni[t] >= THRESH) {
                if (k < LL) s_fidx[k] = t;
                ++k;
            }
        }
    }
    __syncthreads();

    // Build records with exact-f32 reconstruction of weights.
    const int cnt = s_cnt;
    if (tid < LL) {
        int4 r = make_int4(0, -1, 0, 0);
        if (tid < cnt) {
            const int t = s_fidx[tid];
            float iold = 0.0f;
            if (t > 0) {
                const float np = s_ni[t - 1];
                iold = (np >= THRESH) ? __fsub_rn(np, 1.0f) : np;
            }
            const float cur = __fsub_rn(1.0f, iold);
            float carry = 0.0f;
            int prev = -1;
            if (tid > 0) {
                prev = s_fidx[tid - 1];
                float piold = 0.0f;
                if (prev > 0) {
                    const float np = s_ni[prev - 1];
                    piold = (np >= THRESH) ? __fsub_rn(np, 1.0f) : np;
                }
                const float pcur = __fsub_rn(1.0f, piold);
                carry = __fsub_rn(s_alpha[prev], pcur);
            }
            r.x = prev;
            r.y = t;
            r.z = __float_as_int(carry);
            r.w = __float_as_int(cur);
        }
        g_rec[b * LL + tid] = r;
    }
    if (tid == 0) g_cnt[b] = cnt;
}

// ---------------------------------------------------------------------------
// Kernel 2: out[b,k,:] = carry*h[s] + sum alpha_t*h[t] + cur*h[e]
// Manual 4-wide load batching + dual accumulators for MLP.
// ---------------------------------------------------------------------------
__global__ void __launch_bounds__(128) cif_gather_kernel(
    const float* __restrict__ hidden,   // [B,T,H]
    float* __restrict__ out)            // [B,L,H]
{
    const int k = blockIdx.x;
    const int b = blockIdx.y;
    const int c = threadIdx.x * 4;

    float4 acc0 = make_float4(0.f, 0.f, 0.f, 0.f);
    float4 acc1 = make_float4(0.f, 0.f, 0.f, 0.f);

    if (k < g_cnt[b]) {
        const int4 r = g_rec[b * LL + k];
        const int   s  = r.x;
        const int   e  = r.y;
        const float wc = __int_as_float(r.z);
        const float we = __int_as_float(r.w);

        const float* hb = hidden + (size_t)b * TT * HH + c;
        const float* wa = g_walpha + b * TT;

        if (s >= 0) {
            const float4 h4 = __ldcs(reinterpret_cast<const float4*>(hb + (size_t)s * HH));
            acc0.x += wc * h4.x; acc0.y += wc * h4.y;
            acc0.z += wc * h4.z; acc0.w += wc * h4.w;
        }

        int t = s + 1;
        for (; t + 4 <= e; t += 4) {
            const float w0 = wa[t];
            const float w1 = wa[t + 1];
            const float w2 = wa[t + 2];
            const float w3 = wa[t + 3];
            const float4 h0 = __ldcs(reinterpret_cast<const float4*>(hb + (size_t)t * HH));
            const float4 h1 = __ldcs(reinterpret_cast<const float4*>(hb + (size_t)(t + 1) * HH));
            const float4 h2 = __ldcs(reinterpret_cast<const float4*>(hb + (size_t)(t + 2) * HH));
            const float4 h3 = __ldcs(reinterpret_cast<const float4*>(hb + (size_t)(t + 3) * HH));
            acc0.x += w0 * h0.x; acc0.y += w0 * h0.y; acc0.z += w0 * h0.z; acc0.w += w0 * h0.w;
            acc1.x += w1 * h1.x; acc1.y += w1 * h1.y; acc1.z += w1 * h1.z; acc1.w += w1 * h1.w;
            acc0.x += w2 * h2.x; acc0.y += w2 * h2.y; acc0.z += w2 * h2.z; acc0.w += w2 * h2.w;
            acc1.x += w3 * h3.x; acc1.y += w3 * h3.y; acc1.z += w3 * h3.z; acc1.w += w3 * h3.w;
        }
        for (; t < e; ++t) {
            const float w = wa[t];
            const float4 h4 = __ldcs(reinterpret_cast<const float4*>(hb + (size_t)t * HH));
            acc0.x += w * h4.x; acc0.y += w * h4.y;
            acc0.z += w * h4.z; acc0.w += w * h4.w;
        }
        {
            const float4 h4 = __ldcs(reinterpret_cast<const float4*>(hb + (size_t)e * HH));
            acc1.x += we * h4.x; acc1.y += we * h4.y;
            acc1.z += we * h4.z; acc1.w += we * h4.w;
        }
    }
    acc0.x += acc1.x; acc0.y += acc1.y; acc0.z += acc1.z; acc0.w += acc1.w;
    __stcs(reinterpret_cast<float4*>(out + ((size_t)b * LL + k) * HH + c), acc0);
}

// ---------------------------------------------------------------------------
extern "C" void kernel_launch(void* const* d_in, const int* in_sizes, int n_in,
                              void* d_out, int out_size)
{
    const float* hidden = (const float*)d_in[0];   // [B,T,H] f32
    const float* alphas = (const float*)d_in[1];   // [B,T]   f32
    const int*   tlen   = (const int*)  d_in[2];   // [B]     i32
    float* out = (float*)d_out;                    // [B,L,H] f32

    cif_scan_kernel<<<BB, NTHR>>>(alphas, tlen);
    dim3 grid(LL, BB);
    cif_gather_kernel<<<grid, 128>>>(hidden, out);
}

// round 7
// speedup vs baseline: 1.7482x; 1.0782x over previous
#include <cuda_runtime.h>
#include <cstdint>

// Problem constants (fixed by the reference).
#define BB 32
#define TT 2000
#define LL 256
#define HH 512
#define NTHR 256
#define FRAMES_PER_THR 8   // 256*8 = 2048 >= 2000
#define T4 (TT / 4)        // 500 float4 groups
#define THRESH 0.95f

// Scratch (allocation-free rule: __device__ globals).
__device__ float g_walpha[BB * TT];   // rescaled alphas
__device__ int4  g_rec[BB * LL];      // {seg_start, seg_end, carry_bits, cur_bits}
__device__ int   g_cnt[BB];           // fires per batch (clamped to LL)

// One CIF recurrence step, forced to the 12-cycle data chain:
//   add.f32 (4) -> setp.ge.f32 (4, pred-as-data) -> selp.f32 (4)
// sub.f32 runs in parallel with setp. No branches, no predicated guards.
__device__ __forceinline__ void cif_step(float& integ, float a, float& ni_out)
{
    float ni, nim;
    asm("add.f32 %0, %2, %3;\n\t"
        "sub.f32 %1, %0, 0f3F800000;"            // nim = ni - 1.0f
        : "=f"(ni), "=f"(nim) : "f"(integ), "f"(a));
    asm("{\n\t"
        ".reg .pred p;\n\t"
        "setp.ge.f32 p, %1, 0f3F733333;\n\t"     // ni >= 0.95f
        "selp.f32 %0, %2, %1, p;\n\t"
        "}"
        : "=f"(integ) : "f"(ni), "f"(nim));
    ni_out = ni;
}

// ---------------------------------------------------------------------------
// Kernel 1: per-batch rescale + minimal serial recurrence + parallel rebuild.
// ---------------------------------------------------------------------------
__global__ void __launch_bounds__(NTHR, 1) cif_scan_kernel(
    const float* __restrict__ alphas,   // [B,T]
    const int*   __restrict__ tlen)     // [B]
{
    __shared__ __align__(16) float s_alpha[TT];
    __shared__ __align__(16) float s_ni[TT];
    __shared__ double s_wred[8];
    __shared__ float  s_scale;
    __shared__ int    s_tsum[NTHR];
    __shared__ int    s_fidx[LL];
    __shared__ int    s_cnt;

    const int b    = blockIdx.x;
    const int tid  = threadIdx.x;
    const int lane = tid & 31;
    const int wid  = tid >> 5;

    // ---- Phase 1: load alphas (float4), double sum via warp shuffles ----
    const float4* ain = reinterpret_cast<const float4*>(alphas + b * TT);
    float4* asm4 = reinterpret_cast<float4*>(s_alpha);
    double local = 0.0;
    #pragma unroll
    for (int i = 0; i < 2; ++i) {
        const int idx = tid + i * NTHR;
        if (idx < T4) {
            const float4 v = ain[idx];
            asm4[idx] = v;
            local += (double)v.x + (double)v.y + (double)v.z + (double)v.w;
        }
    }
    #pragma unroll
    for (int off = 16; off > 0; off >>= 1)
        local += __shfl_down_sync(0xffffffffu, local, off);
    if (lane == 0) s_wred[wid] = local;
    __syncthreads();
    if (tid == 0) {
        double s = 0.0;
        #pragma unroll
        for (int w = 0; w < 8; ++w) s += s_wred[w];
        s_scale = __fdiv_rn((float)tlen[b], (float)s);
    }
    __syncthreads();

    // ---- Rescale (smem + spill to global) ----
    const float scale = s_scale;
    float4* wout = reinterpret_cast<float4*>(g_walpha + b * TT);
    #pragma unroll
    for (int i = 0; i < 2; ++i) {
        const int idx = tid + i * NTHR;
        if (idx < T4) {
            float4 v = asm4[idx];
            v.x = __fmul_rn(v.x, scale); v.y = __fmul_rn(v.y, scale);
            v.z = __fmul_rn(v.z, scale); v.w = __fmul_rn(v.w, scale);
            asm4[idx] = v;
            wout[idx] = v;
        }
    }
    __syncthreads();

    // ---- Phase 2: minimal serial recurrence (thread 0), prefetched ----
    if (tid == 0) {
        float integ = 0.0f;
        const float4* a4 = reinterpret_cast<const float4*>(s_alpha);
        float4* n4 = reinterpret_cast<float4*>(s_ni);
        float4 av = a4[0];
        #pragma unroll 2
        for (int t4 = 0; t4 < T4; ++t4) {
            const int nidx = (t4 + 1 < T4) ? t4 + 1 : t4;
            const float4 nx = a4[nidx];       // prefetch off-chain
            float4 nv;
            cif_step(integ, av.x, nv.x);
            cif_step(integ, av.y, nv.y);
            cif_step(integ, av.z, nv.z);
            cif_step(integ, av.w, nv.w);
            n4[t4] = nv;
            av = nx;
        }
    }
    __syncthreads();

    // ---- Phase 3: parallel rebuild of fire records from ni_t ----
    const int t0 = tid * FRAMES_PER_THR;
    int cnt_local = 0;
    #pragma unroll
    for (int j = 0; j < FRAMES_PER_THR; ++j) {
        const int t = t0 + j;
        if (t < TT && s_ni[t] >= THRESH) ++cnt_local;
    }
    s_tsum[tid] = cnt_local;
    __syncthreads();

    {   // exclusive prefix sum over 256 counts
        int v = s_tsum[tid];
        int x = v;
        #pragma unroll
        for (int d = 1; d < 32; d <<= 1) {
            int y = __shfl_up_sync(0xffffffffu, x, d);
            if (lane >= d) x += y;
        }
        __syncthreads();
        if (lane == 31) s_tsum[wid] = x;
        __syncthreads();
        int warp_base = 0, total = 0;
        #pragma unroll
        for (int w = 0; w < 8; ++w) {
            const int wv = s_tsum[w];
            warp_base += (w < wid) ? wv : 0;
            total += wv;
        }
        __syncthreads();
        s_tsum[tid] = warp_base + x - v;
        if (tid == 0) s_cnt = (total < LL) ? total : LL;
    }
    __syncthreads();

    {   // compact fire frame indices
        int k = s_tsum[tid];
        #pragma unroll
        for (int j = 0; j < FRAMES_PER_THR; ++j) {
            const int t = t0 + j;
            if (t < TT && s_ni[t] >= THRESH) {
                if (k < LL) s_fidx[k] = t;
                ++k;
            }
        }
    }
    __syncthreads();

    // Build records with exact-f32 reconstruction of weights.
    const int cnt = s_cnt;
    if (tid < LL) {
        int4 r = make_int4(0, -1, 0, 0);
        if (tid < cnt) {
            const int t = s_fidx[tid];
            float iold = 0.0f;
            if (t > 0) {
                const float np = s_ni[t - 1];
                iold = (np >= THRESH) ? __fsub_rn(np, 1.0f) : np;
            }
            const float cur = __fsub_rn(1.0f, iold);
            float carry = 0.0f;
            int prev = -1;
            if (tid > 0) {
                prev = s_fidx[tid - 1];
                float piold = 0.0f;
                if (prev > 0) {
                    const float np = s_ni[prev - 1];
                    piold = (np >= THRESH) ? __fsub_rn(np, 1.0f) : np;
                }
                const float pcur = __fsub_rn(1.0f, piold);
                carry = __fsub_rn(s_alpha[prev], pcur);
            }
            r.x = prev;
            r.y = t;
            r.z = __float_as_int(carry);
            r.w = __float_as_int(cur);
        }
        g_rec[b * LL + tid] = r;
    }
    if (tid == 0) g_cnt[b] = cnt;
}

// ---------------------------------------------------------------------------
// Kernel 2 (R3 measured-best form): out[b,k,:] = carry*h[s] + sum + cur*h[e]
// Grid (L, B); 128 threads; float4 per thread. Streaming HBM-bound.
// ---------------------------------------------------------------------------
__global__ void __launch_bounds__(128) cif_gather_kernel(
    const float* __restrict__ hidden,   // [B,T,H]
    float* __restrict__ out)            // [B,L,H]
{
    const int k = blockIdx.x;
    const int b = blockIdx.y;
    const int c = threadIdx.x * 4;      // channel base

    float4 acc = make_float4(0.f, 0.f, 0.f, 0.f);

    if (k < g_cnt[b]) {
        const int4 r = g_rec[b * LL + k];
        const int   s  = r.x;
        const int   e  = r.y;
        const float wc = __int_as_float(r.z);
        const float we = __int_as_float(r.w);

        const float* hb = hidden + (size_t)b * TT * HH;
        const float* wa = g_walpha + b * TT;

        if (s >= 0) {
            const float4 h4 = __ldcs(reinterpret_cast<const float4*>(hb + (size_t)s * HH + c));
            acc.x += wc * h4.x; acc.y += wc * h4.y; acc.z += wc * h4.z; acc.w += wc * h4.w;
        }
        #pragma unroll 4
        for (int t = s + 1; t < e; ++t) {
            const float w = wa[t];
            const float4 h4 = __ldcs(reinterpret_cast<const float4*>(hb + (size_t)t * HH + c));
            acc.x += w * h4.x; acc.y += w * h4.y; acc.z += w * h4.z; acc.w += w * h4.w;
        }
        {
            const float4 h4 = __ldcs(reinterpret_cast<const float4*>(hb + (size_t)e * HH + c));
            acc.x += we * h4.x; acc.y += we * h4.y; acc.z += we * h4.z; acc.w += we * h4.w;
        }
    }
    __stcs(reinterpret_cast<float4*>(out + ((size_t)b * LL + k) * HH + c), acc);
}

// ---------------------------------------------------------------------------
extern "C" void kernel_launch(void* const* d_in, const int* in_sizes, int n_in,
                              void* d_out, int out_size)
{
    const float* hidden = (const float*)d_in[0];   // [B,T,H] f32
    const float* alphas = (const float*)d_in[1];   // [B,T]   f32
    const int*   tlen   = (const int*)  d_in[2];   // [B]     i32
    float* out = (float*)d_out;                    // [B,L,H] f32

    cif_scan_kernel<<<BB, NTHR>>>(alphas, tlen);
    dim3 grid(LL, BB);
    cif_gather_kernel<<<grid, 128>>>(hidden, out);
}